// round 11
// baseline (speedup 1.0000x reference)
#include <cuda_runtime.h>
#include <cuda_bf16.h>
#include <cstdint>

// ---------------------------------------------------------------------------
// total = -(1/L) * sum_i dot(q_hat_i, q_real_i)
//       + sum_{i,j} max(0, <pred_i, gt_j> - <pred_i, gt_i> + 1)
// L=8192, B=4096, D=1024.
// R11: persistent GEMM (304 CTAs, dynamic tile tickets) to pack the 3.46-wave
// schedule that static 1024-CTA launch rounded to 4 waves. GEMM inner loop =
// R8's proven form (fp8 e4m3, 256 thr, warp tile 64x32, 3-stage, 2 CTA/SM).
// prep: 8 rows/block. finalize fused via completion counter + local_done spin.
// ---------------------------------------------------------------------------

#define L_DIM 8192
#define B_DIM 4096
#define D_DIM 1024

struct Accum {
    double glob;
    double local;
    unsigned int tile;        // dynamic tile ticket
    unsigned int gdone;       // completed tiles
    unsigned int lticket;
    unsigned int local_done;
};
__device__ Accum g_acc;
__device__ float g_pos[B_DIM];
// FP8 operand buffers (4 MB each), stored as uint32 (4 e4m3 per word)
__device__ uint32_t g_predq[(size_t)B_DIM * D_DIM / 4];
__device__ uint32_t g_gtq[(size_t)B_DIM * D_DIM / 4];

#define NUM_TILES 1024           // 32 x 32 tiles of 128x128
#define GEMM_CTAS 304            // 2 per SM x 152 SMs
#define NUM_LOCAL_CTAS 1024
#define PREP_ROWS 8

// ---------------------------------------------------------------------------
__device__ __forceinline__ uint32_t smem_u32(const void* p) {
    uint32_t a;
    asm("{ .reg .u64 t; cvta.to.shared.u64 t, %1; cvt.u32.u64 %0, t; }"
        : "=r"(a) : "l"(p));
    return a;
}

__device__ __forceinline__ void cp_async16(uint32_t smem, const void* gmem) {
    asm volatile("cp.async.cg.shared.global [%0], [%1], 16;"
                 :: "r"(smem), "l"(gmem) : "memory");
}
#define CP_COMMIT() asm volatile("cp.async.commit_group;" ::: "memory")
#define CP_WAIT1()  asm volatile("cp.async.wait_group 1;" ::: "memory")

#define LDSM_X4(r0, r1, r2, r3, addr) \
    asm volatile("ldmatrix.sync.aligned.m8n8.x4.shared.b16 {%0,%1,%2,%3}, [%4];" \
                 : "=r"(r0), "=r"(r1), "=r"(r2), "=r"(r3) : "r"(addr))

// FP8 e4m3 MMA, k32, fp32 accumulation.
__device__ __forceinline__ void mma16832(float* c, const uint32_t* a,
                                         uint32_t b0, uint32_t b1) {
    asm volatile(
        "mma.sync.aligned.m16n8k32.row.col.f32.e4m3.e4m3.f32 "
        "{%0,%1,%2,%3}, {%4,%5,%6,%7}, {%8,%9}, {%0,%1,%2,%3};"
        : "+f"(c[0]), "+f"(c[1]), "+f"(c[2]), "+f"(c[3])
        : "r"(a[0]), "r"(a[1]), "r"(a[2]), "r"(a[3]), "r"(b0), "r"(b1));
}

__device__ __forceinline__ uint32_t pack_e4m3x4(float4 v) {
    uint16_t lo, hi;
    asm("cvt.rn.satfinite.e4m3x2.f32 %0, %1, %2;" : "=h"(lo) : "f"(v.y), "f"(v.x));
    asm("cvt.rn.satfinite.e4m3x2.f32 %0, %1, %2;" : "=h"(hi) : "f"(v.w), "f"(v.z));
    return (uint32_t)lo | ((uint32_t)hi << 16);
}

// ---------------------------------------------------------------------------
// Kernel 1: fp32 -> e4m3 for pred/gt + pos[i] = dot(pred_i, gt_i) (exact fp32)
// 8 rows per block (16 independent 16B loads in flight per thread).
// grid = B_DIM/8, 256 threads.
// ---------------------------------------------------------------------------
__global__ void prep_kernel(const float* __restrict__ pred,
                            const float* __restrict__ gt) {
    const int r0 = blockIdx.x * PREP_ROWS;
    const int t = threadIdx.x;

    float4 pv[PREP_ROWS], gv[PREP_ROWS];
    #pragma unroll
    for (int rr = 0; rr < PREP_ROWS; rr++) {
        pv[rr] = ((const float4*)(pred + (size_t)(r0 + rr) * D_DIM))[t];
        gv[rr] = ((const float4*)(gt + (size_t)(r0 + rr) * D_DIM))[t];
    }

    __shared__ float ws[PREP_ROWS][8];
    #pragma unroll
    for (int rr = 0; rr < PREP_ROWS; rr++) {
        g_predq[(size_t)(r0 + rr) * (D_DIM / 4) + t] = pack_e4m3x4(pv[rr]);
        g_gtq[(size_t)(r0 + rr) * (D_DIM / 4) + t] = pack_e4m3x4(gv[rr]);

        float acc = pv[rr].x * gv[rr].x + pv[rr].y * gv[rr].y +
                    pv[rr].z * gv[rr].z + pv[rr].w * gv[rr].w;
        #pragma unroll
        for (int o = 16; o > 0; o >>= 1)
            acc += __shfl_xor_sync(0xFFFFFFFFu, acc, o);
        if ((t & 31) == 0) ws[rr][t >> 5] = acc;
    }
    __syncthreads();
    if (t < PREP_ROWS) {
        float s = 0.f;
        #pragma unroll
        for (int w = 0; w < 8; w++) s += ws[t][w];
        g_pos[r0 + t] = s;
    }
}

// ---------------------------------------------------------------------------
// Kernel 2: local loss partial (side stream; overlaps prep + GEMM).
// ---------------------------------------------------------------------------
__global__ void local_kernel(const float* __restrict__ a,
                             const float* __restrict__ b) {
    const size_t n4 = (size_t)L_DIM * D_DIM / 4;
    float acc = 0.f;
    for (size_t i = (size_t)blockIdx.x * blockDim.x + threadIdx.x; i < n4;
         i += (size_t)gridDim.x * blockDim.x) {
        float4 av = ((const float4*)a)[i];
        float4 bv = ((const float4*)b)[i];
        acc += av.x * bv.x + av.y * bv.y + av.z * bv.z + av.w * bv.w;
    }
    #pragma unroll
    for (int o = 16; o > 0; o >>= 1)
        acc += __shfl_xor_sync(0xFFFFFFFFu, acc, o);
    __shared__ float ws[8];
    const int t = threadIdx.x;
    if ((t & 31) == 0) ws[t >> 5] = acc;
    __syncthreads();
    if (t == 0) {
        float s = 0.f;
        #pragma unroll
        for (int w = 0; w < 8; w++) s += ws[w];
        atomicAdd(&g_acc.local, (double)s);
        __threadfence();
        unsigned int tk = atomicAdd(&g_acc.lticket, 1u);
        if (tk == NUM_LOCAL_CTAS - 1) {
            __threadfence();
            atomicExch(&g_acc.local_done, 1u);
        }
    }
}

// ---------------------------------------------------------------------------
// Kernel 3: persistent FP8 GEMM + fused hinge + fused finalize.
// grid = 304 CTAs, 256 threads (8 warps: 2(m) x 4(n), warp tile 64x32).
// Each CTA loops over dynamically-ticketed 128x128 tiles.
// 3-stage cp.async pipeline, 2 CTAs/SM.
// ---------------------------------------------------------------------------
static constexpr int GEMM_SMEM_DYN = 3 * 32768;  // 96 KB

__global__ void __launch_bounds__(256, 2) gemm_hinge_kernel(float* out) {
    extern __shared__ char smem_raw[];
    const uint32_t sb = smem_u32(smem_raw);
    const int tid = threadIdx.x;
    const int wid = tid >> 5;
    const int lane = tid & 31;
    const int warp_m = wid >> 2;   // 0..1
    const int warp_n = wid & 3;    // 0..3

    // Precomputed LDSM base offsets (tile-invariant).
    uint32_t a_base[4], b_base[2];
    #pragma unroll
    for (int mt = 0; mt < 4; mt++) {
        const int row = warp_m * 64 + mt * 16 + (lane & 15);
        a_base[mt] = row * 128 + (((lane >> 4) ^ (row & 7)) << 4);
    }
    #pragma unroll
    for (int nt = 0; nt < 2; nt++) {
        const int row = warp_n * 32 + nt * 16 + (lane & 15);
        b_base[nt] = row * 128 + (((lane >> 4) ^ (row & 7)) << 4);
    }

    __shared__ unsigned int tile_s;
    __shared__ float warpsum[8];

    while (true) {
        // Barrier also orders: previous tile's warpsum read (tid 0) and all
        // warps' final-stage smem reads happen-before this tile's writes.
        __syncthreads();
        if (tid == 0) tile_s = atomicAdd(&g_acc.tile, 1u);
        __syncthreads();
        const unsigned int tile = tile_s;
        if (tile >= NUM_TILES) break;
        const int bx = tile & 31;       // N tile
        const int by = tile >> 5;       // M tile

        const uint8_t* __restrict__ Ab =
            (const uint8_t*)g_predq + (size_t)by * 128 * D_DIM;
        const uint8_t* __restrict__ Bb =
            (const uint8_t*)g_gtq + (size_t)bx * 128 * D_DIM;

        float acc[4][4][4];
        #pragma unroll
        for (int i = 0; i < 4; i++)
            #pragma unroll
            for (int j = 0; j < 4; j++)
                #pragma unroll
                for (int e = 0; e < 4; e++) acc[i][j][e] = 0.f;

        auto load_stage = [&](int kc, int st) {
            const uint32_t baseA = sb + st * 32768;
            const uint32_t baseB = baseA + 16384;
            #pragma unroll
            for (int i = 0; i < 4; i++) {
                const int idx = tid + i * 256;      // 0..1023
                const int row = idx >> 3;           // 0..127
                const int c = idx & 7;
                const uint32_t soff = row * 128 + ((c ^ (row & 7)) << 4);
                cp_async16(baseA + soff, Ab + (size_t)row * D_DIM + kc * 128 + c * 16);
                cp_async16(baseB + soff, Bb + (size_t)row * D_DIM + kc * 128 + c * 16);
            }
        };

        load_stage(0, 0); CP_COMMIT();
        load_stage(1, 1); CP_COMMIT();

        #pragma unroll 1
        for (int kc = 0; kc < 8; ++kc) {
            CP_WAIT1();          // stage kc resident
            __syncthreads();     // all warps done with the stage we refill
            if (kc + 2 < 8) load_stage(kc + 2, (kc + 2) % 3);
            CP_COMMIT();         // uniform group count even when empty

            const uint32_t baseA = sb + (kc % 3) * 32768;
            const uint32_t baseB = baseA + 16384;

            #pragma unroll
            for (int ks = 0; ks < 4; ks++) {
                const uint32_t cx = (uint32_t)(ks * 2) << 4;
                uint32_t a[4][4], b[2][4];
                #pragma unroll
                for (int mt = 0; mt < 4; mt++)
                    LDSM_X4(a[mt][0], a[mt][1], a[mt][2], a[mt][3],
                            baseA + (a_base[mt] ^ cx));
                #pragma unroll
                for (int nt = 0; nt < 2; nt++)
                    LDSM_X4(b[nt][0], b[nt][1], b[nt][2], b[nt][3],
                            baseB + (b_base[nt] ^ cx));
                #pragma unroll
                for (int mt = 0; mt < 4; mt++)
                    #pragma unroll
                    for (int nt = 0; nt < 4; nt++)
                        mma16832(acc[mt][nt], a[mt],
                                 b[nt >> 1][nt & 1], b[nt >> 1][(nt & 1) + 2]);
            }
        }

        // ---- fused hinge epilogue ----
        float partial = 0.f;
        #pragma unroll
        for (int mt = 0; mt < 4; mt++) {
            const int r0 = by * 128 + warp_m * 64 + mt * 16 + (lane >> 2);
            const float p0 = __ldg(&g_pos[r0]) - 1.0f;
            const float p1 = __ldg(&g_pos[r0 + 8]) - 1.0f;
            #pragma unroll
            for (int nt = 0; nt < 4; nt++) {
                partial += fmaxf(acc[mt][nt][0] - p0, 0.f);
                partial += fmaxf(acc[mt][nt][1] - p0, 0.f);
                partial += fmaxf(acc[mt][nt][2] - p1, 0.f);
                partial += fmaxf(acc[mt][nt][3] - p1, 0.f);
            }
        }

        #pragma unroll
        for (int o = 16; o > 0; o >>= 1)
            partial += __shfl_xor_sync(0xFFFFFFFFu, partial, o);
        if (lane == 0) warpsum[wid] = partial;
        __syncthreads();
        if (tid == 0) {
            float s = 0.f;
            #pragma unroll
            for (int w = 0; w < 8; w++) s += warpsum[w];
            atomicAdd(&g_acc.glob, (double)s);
            __threadfence();
            unsigned int dk = atomicAdd(&g_acc.gdone, 1u);
            if (dk == NUM_TILES - 1) {
                // Fused finalize: all tiles accumulated; wait for local.
                while (atomicAdd(&g_acc.local_done, 0u) == 0u) {}
                __threadfence();
                const double gv = *((volatile double*)&g_acc.glob);
                const double lv = *((volatile double*)&g_acc.local);
                out[0] = (float)(gv - lv / (double)L_DIM);
            }
        }
    }
}

// ---------------------------------------------------------------------------
extern "C" void kernel_launch(void* const* d_in, const int* in_sizes, int n_in,
                              void* d_out, int out_size) {
    const float* q_hat  = (const float*)d_in[0];
    const float* q_real = (const float*)d_in[1];
    const float* gt     = (const float*)d_in[2];
    const float* pred   = (const float*)d_in[3];

    (void)in_sizes; (void)n_in; (void)out_size;

    // One-time setup on the first (non-captured) correctness call.
    static cudaStream_t s_side = nullptr;
    static cudaEvent_t ev_fork = nullptr, ev_join = nullptr;
    static void* accum_ptr = nullptr;
    if (!accum_ptr) {
        cudaFuncSetAttribute(gemm_hinge_kernel,
                             cudaFuncAttributeMaxDynamicSharedMemorySize,
                             GEMM_SMEM_DYN);
        cudaStreamCreateWithFlags(&s_side, cudaStreamNonBlocking);
        cudaEventCreateWithFlags(&ev_fork, cudaEventDisableTiming);
        cudaEventCreateWithFlags(&ev_join, cudaEventDisableTiming);
        cudaGetSymbolAddress(&accum_ptr, g_acc);
    }

    // Main stream: memset -> prep -> persistent gemm(+finalize)
    // Side stream: local_kernel (independent; overlaps prep + gemm)
    cudaMemsetAsync(accum_ptr, 0, sizeof(Accum), 0);
    cudaEventRecord(ev_fork, 0);
    cudaStreamWaitEvent(s_side, ev_fork, 0);

    prep_kernel<<<B_DIM / PREP_ROWS, 256>>>(pred, gt);
    local_kernel<<<NUM_LOCAL_CTAS, 256, 0, s_side>>>(q_hat, q_real);

    gemm_hinge_kernel<<<GEMM_CTAS, 256, GEMM_SMEM_DYN>>>((float*)d_out);

    // Graph must join the side stream before capture ends.
    cudaEventRecord(ev_join, s_side);
    cudaStreamWaitEvent(0, ev_join, 0);
}

// round 12
// speedup vs baseline: 1.0206x; 1.0206x over previous
#include <cuda_runtime.h>
#include <cuda_bf16.h>
#include <cstdint>

// ---------------------------------------------------------------------------
// total = -(1/L) * sum_i dot(q_hat_i, q_real_i)
//       + sum_{i,j} max(0, <pred_i, gt_j> - <pred_i, gt_i> + 1)
// L=8192, B=4096, D=1024.
// R12: R10 base (best: static 1024-CTA fp8 GEMM, warp tile 64x32, 3-stage,
// 2 CTA/SM, prep ROWS=4, side-stream local, fused finalize) with the GEMM
// mainloop reordered (sync -> load -> commit -> wait_group 2 -> compute) and
// fully unrolled over kc so stage indices/swizzle XORs are compile-time.
// R11 lesson: persistence can't fix wave quantization of equal tiles.
// ---------------------------------------------------------------------------

#define L_DIM 8192
#define B_DIM 4096
#define D_DIM 1024

struct Accum {
    double glob;
    double local;
    unsigned int gticket;
    unsigned int lticket;
    unsigned int local_done;
};
__device__ Accum g_acc;
__device__ float g_pos[B_DIM];
// FP8 operand buffers (4 MB each), stored as uint32 (4 e4m3 per word)
__device__ uint32_t g_predq[(size_t)B_DIM * D_DIM / 4];
__device__ uint32_t g_gtq[(size_t)B_DIM * D_DIM / 4];

#define NUM_GEMM_CTAS (32 * 32)
#define NUM_LOCAL_CTAS 1024
#define PREP_ROWS 4

// ---------------------------------------------------------------------------
__device__ __forceinline__ uint32_t smem_u32(const void* p) {
    uint32_t a;
    asm("{ .reg .u64 t; cvta.to.shared.u64 t, %1; cvt.u32.u64 %0, t; }"
        : "=r"(a) : "l"(p));
    return a;
}

__device__ __forceinline__ void cp_async16(uint32_t smem, const void* gmem) {
    asm volatile("cp.async.cg.shared.global [%0], [%1], 16;"
                 :: "r"(smem), "l"(gmem) : "memory");
}
#define CP_COMMIT() asm volatile("cp.async.commit_group;" ::: "memory")
#define CP_WAIT2()  asm volatile("cp.async.wait_group 2;" ::: "memory")

#define LDSM_X4(r0, r1, r2, r3, addr) \
    asm volatile("ldmatrix.sync.aligned.m8n8.x4.shared.b16 {%0,%1,%2,%3}, [%4];" \
                 : "=r"(r0), "=r"(r1), "=r"(r2), "=r"(r3) : "r"(addr))

// FP8 e4m3 MMA, k32, fp32 accumulation.
__device__ __forceinline__ void mma16832(float* c, const uint32_t* a,
                                         uint32_t b0, uint32_t b1) {
    asm volatile(
        "mma.sync.aligned.m16n8k32.row.col.f32.e4m3.e4m3.f32 "
        "{%0,%1,%2,%3}, {%4,%5,%6,%7}, {%8,%9}, {%0,%1,%2,%3};"
        : "+f"(c[0]), "+f"(c[1]), "+f"(c[2]), "+f"(c[3])
        : "r"(a[0]), "r"(a[1]), "r"(a[2]), "r"(a[3]), "r"(b0), "r"(b1));
}

__device__ __forceinline__ uint32_t pack_e4m3x4(float4 v) {
    uint16_t lo, hi;
    asm("cvt.rn.satfinite.e4m3x2.f32 %0, %1, %2;" : "=h"(lo) : "f"(v.y), "f"(v.x));
    asm("cvt.rn.satfinite.e4m3x2.f32 %0, %1, %2;" : "=h"(hi) : "f"(v.w), "f"(v.z));
    return (uint32_t)lo | ((uint32_t)hi << 16);
}

// ---------------------------------------------------------------------------
// Kernel 1: fp32 -> e4m3 for pred/gt + pos[i] = dot(pred_i, gt_i) (exact fp32)
// 4 rows per block (8 independent 16B loads in flight per thread).
// ---------------------------------------------------------------------------
__global__ void prep_kernel(const float* __restrict__ pred,
                            const float* __restrict__ gt) {
    const int r0 = blockIdx.x * PREP_ROWS;
    const int t = threadIdx.x;

    float4 pv[PREP_ROWS], gv[PREP_ROWS];
    #pragma unroll
    for (int rr = 0; rr < PREP_ROWS; rr++) {
        pv[rr] = ((const float4*)(pred + (size_t)(r0 + rr) * D_DIM))[t];
        gv[rr] = ((const float4*)(gt + (size_t)(r0 + rr) * D_DIM))[t];
    }

    __shared__ float ws[PREP_ROWS][8];
    #pragma unroll
    for (int rr = 0; rr < PREP_ROWS; rr++) {
        g_predq[(size_t)(r0 + rr) * (D_DIM / 4) + t] = pack_e4m3x4(pv[rr]);
        g_gtq[(size_t)(r0 + rr) * (D_DIM / 4) + t] = pack_e4m3x4(gv[rr]);

        float acc = pv[rr].x * gv[rr].x + pv[rr].y * gv[rr].y +
                    pv[rr].z * gv[rr].z + pv[rr].w * gv[rr].w;
        #pragma unroll
        for (int o = 16; o > 0; o >>= 1)
            acc += __shfl_xor_sync(0xFFFFFFFFu, acc, o);
        if ((t & 31) == 0) ws[rr][t >> 5] = acc;
    }
    __syncthreads();
    if (t < PREP_ROWS) {
        float s = 0.f;
        #pragma unroll
        for (int w = 0; w < 8; w++) s += ws[t][w];
        g_pos[r0 + t] = s;
    }
}

// ---------------------------------------------------------------------------
// Kernel 2: local loss partial (side stream; overlaps prep + GEMM).
// Last block sets local_done (release) for the GEMM's fused finalize.
// ---------------------------------------------------------------------------
__global__ void local_kernel(const float* __restrict__ a,
                             const float* __restrict__ b) {
    const size_t n4 = (size_t)L_DIM * D_DIM / 4;
    float acc = 0.f;
    for (size_t i = (size_t)blockIdx.x * blockDim.x + threadIdx.x; i < n4;
         i += (size_t)gridDim.x * blockDim.x) {
        float4 av = ((const float4*)a)[i];
        float4 bv = ((const float4*)b)[i];
        acc += av.x * bv.x + av.y * bv.y + av.z * bv.z + av.w * bv.w;
    }
    #pragma unroll
    for (int o = 16; o > 0; o >>= 1)
        acc += __shfl_xor_sync(0xFFFFFFFFu, acc, o);
    __shared__ float ws[8];
    const int t = threadIdx.x;
    if ((t & 31) == 0) ws[t >> 5] = acc;
    __syncthreads();
    if (t == 0) {
        float s = 0.f;
        #pragma unroll
        for (int w = 0; w < 8; w++) s += ws[w];
        atomicAdd(&g_acc.local, (double)s);
        __threadfence();
        unsigned int tk = atomicAdd(&g_acc.lticket, 1u);
        if (tk == NUM_LOCAL_CTAS - 1) {
            __threadfence();
            atomicExch(&g_acc.local_done, 1u);
        }
    }
}

// ---------------------------------------------------------------------------
// Kernel 3: FP8 GEMM 128x128 tile + fused hinge + fused finalize.
// grid (32,32), 256 thr, 8 warps 2x4, warp tile 64x32, 3-stage cp.async,
// 2 CTAs/SM. Mainloop: sync -> load(kc+2) -> commit -> wait_group(2) ->
// compute(kc); fully unrolled over kc.
// ---------------------------------------------------------------------------
static constexpr int GEMM_SMEM_DYN = 3 * 32768;  // 96 KB

__global__ void __launch_bounds__(256, 2) gemm_hinge_kernel(float* out) {
    extern __shared__ char smem_raw[];
    const uint32_t sb = smem_u32(smem_raw);
    const int tid = threadIdx.x;
    const int wid = tid >> 5;
    const int lane = tid & 31;
    const int warp_m = wid >> 2;   // 0..1
    const int warp_n = wid & 3;    // 0..3

    const uint8_t* __restrict__ Ab =
        (const uint8_t*)g_predq + (size_t)blockIdx.y * 128 * D_DIM;
    const uint8_t* __restrict__ Bb =
        (const uint8_t*)g_gtq + (size_t)blockIdx.x * 128 * D_DIM;

    // Precomputed LDSM base offsets: addr = stage_base + (base ^ (chunk<<4))
    uint32_t a_base[4], b_base[2];
    #pragma unroll
    for (int mt = 0; mt < 4; mt++) {
        const int row = warp_m * 64 + mt * 16 + (lane & 15);
        a_base[mt] = row * 128 + (((lane >> 4) ^ (row & 7)) << 4);
    }
    #pragma unroll
    for (int nt = 0; nt < 2; nt++) {
        const int row = warp_n * 32 + nt * 16 + (lane & 15);
        b_base[nt] = row * 128 + (((lane >> 4) ^ (row & 7)) << 4);
    }

    float acc[4][4][4];
    #pragma unroll
    for (int i = 0; i < 4; i++)
        #pragma unroll
        for (int j = 0; j < 4; j++)
            #pragma unroll
            for (int e = 0; e < 4; e++) acc[i][j][e] = 0.f;

    // Load one K-chunk (128 B per row) of A and B into stage st.
    auto load_stage = [&](int kc, int st) {
        const uint32_t baseA = sb + st * 32768;
        const uint32_t baseB = baseA + 16384;
        #pragma unroll
        for (int i = 0; i < 4; i++) {
            const int idx = tid + i * 256;      // 0..1023
            const int row = idx >> 3;           // 0..127
            const int c = idx & 7;              // 16B chunk within 128B row
            const uint32_t soff = row * 128 + ((c ^ (row & 7)) << 4);
            cp_async16(baseA + soff, Ab + (size_t)row * D_DIM + kc * 128 + c * 16);
            cp_async16(baseB + soff, Bb + (size_t)row * D_DIM + kc * 128 + c * 16);
        }
    };

    load_stage(0, 0); CP_COMMIT();
    load_stage(1, 1); CP_COMMIT();

    #pragma unroll
    for (int kc = 0; kc < 8; ++kc) {
        // Barrier: every warp finished compute(kc-1) -> stage (kc+2)%3
        // (== (kc-1)%3) is safe to overwrite.
        __syncthreads();
        if (kc + 2 < 8) load_stage(kc + 2, (kc + 2) % 3);
        CP_COMMIT();         // uniform group count even when empty
        CP_WAIT2();          // chunk kc resident; kc+1, kc+2 still in flight

        const uint32_t baseA = sb + (kc % 3) * 32768;
        const uint32_t baseB = baseA + 16384;

        #pragma unroll
        for (int ks = 0; ks < 4; ks++) {   // four k32 steps per 128-B chunk
            const uint32_t cx = (uint32_t)(ks * 2) << 4;  // chunk XOR offset
            uint32_t a[4][4], b[2][4];
            #pragma unroll
            for (int mt = 0; mt < 4; mt++)
                LDSM_X4(a[mt][0], a[mt][1], a[mt][2], a[mt][3],
                        baseA + (a_base[mt] ^ cx));
            #pragma unroll
            for (int nt = 0; nt < 2; nt++)
                LDSM_X4(b[nt][0], b[nt][1], b[nt][2], b[nt][3],
                        baseB + (b_base[nt] ^ cx));
            #pragma unroll
            for (int mt = 0; mt < 4; mt++)
                #pragma unroll
                for (int nt = 0; nt < 4; nt++)
                    mma16832(acc[mt][nt], a[mt],
                             b[nt >> 1][nt & 1], b[nt >> 1][(nt & 1) + 2]);
        }
    }

    // ---- fused hinge epilogue ----
    float partial = 0.f;
    #pragma unroll
    for (int mt = 0; mt < 4; mt++) {
        const int r0 = blockIdx.y * 128 + warp_m * 64 + mt * 16 + (lane >> 2);
        const float p0 = __ldg(&g_pos[r0]) - 1.0f;   // v - pos + 1 = v - (pos-1)
        const float p1 = __ldg(&g_pos[r0 + 8]) - 1.0f;
        #pragma unroll
        for (int nt = 0; nt < 4; nt++) {
            partial += fmaxf(acc[mt][nt][0] - p0, 0.f);
            partial += fmaxf(acc[mt][nt][1] - p0, 0.f);
            partial += fmaxf(acc[mt][nt][2] - p1, 0.f);
            partial += fmaxf(acc[mt][nt][3] - p1, 0.f);
        }
    }

    #pragma unroll
    for (int o = 16; o > 0; o >>= 1)
        partial += __shfl_xor_sync(0xFFFFFFFFu, partial, o);
    __shared__ float warpsum[8];
    if (lane == 0) warpsum[wid] = partial;
    __syncthreads();
    if (tid == 0) {
        float s = 0.f;
        #pragma unroll
        for (int w = 0; w < 8; w++) s += warpsum[w];
        atomicAdd(&g_acc.glob, (double)s);
        __threadfence();
        unsigned int tk = atomicAdd(&g_acc.gticket, 1u);
        if (tk == NUM_GEMM_CTAS - 1) {
            // Fused finalize (R9/R10-proven): wait for local completion.
            while (atomicAdd(&g_acc.local_done, 0u) == 0u) {}
            __threadfence();
            const double gv = *((volatile double*)&g_acc.glob);
            const double lv = *((volatile double*)&g_acc.local);
            out[0] = (float)(gv - lv / (double)L_DIM);
        }
    }
}

// ---------------------------------------------------------------------------
extern "C" void kernel_launch(void* const* d_in, const int* in_sizes, int n_in,
                              void* d_out, int out_size) {
    const float* q_hat  = (const float*)d_in[0];
    const float* q_real = (const float*)d_in[1];
    const float* gt     = (const float*)d_in[2];
    const float* pred   = (const float*)d_in[3];

    (void)in_sizes; (void)n_in; (void)out_size;

    // One-time setup on the first (non-captured) correctness call.
    static cudaStream_t s_side = nullptr;
    static cudaEvent_t ev_fork = nullptr, ev_join = nullptr;
    static void* accum_ptr = nullptr;
    if (!accum_ptr) {
        cudaFuncSetAttribute(gemm_hinge_kernel,
                             cudaFuncAttributeMaxDynamicSharedMemorySize,
                             GEMM_SMEM_DYN);
        cudaStreamCreateWithFlags(&s_side, cudaStreamNonBlocking);
        cudaEventCreateWithFlags(&ev_fork, cudaEventDisableTiming);
        cudaEventCreateWithFlags(&ev_join, cudaEventDisableTiming);
        cudaGetSymbolAddress(&accum_ptr, g_acc);
    }

    // Main stream: memset -> prep -> gemm(+finalize)
    // Side stream: local_kernel (independent; overlaps prep + gemm)
    cudaMemsetAsync(accum_ptr, 0, sizeof(Accum), 0);
    cudaEventRecord(ev_fork, 0);
    cudaStreamWaitEvent(s_side, ev_fork, 0);

    prep_kernel<<<B_DIM / PREP_ROWS, 256>>>(pred, gt);
    local_kernel<<<NUM_LOCAL_CTAS, 256, 0, s_side>>>(q_hat, q_real);

    gemm_hinge_kernel<<<dim3(32, 32), 256, GEMM_SMEM_DYN>>>((float*)d_out);

    // Graph must join the side stream before capture ends.
    cudaEventRecord(ev_join, s_side);
    cudaStreamWaitEvent(0, ev_join, 0);
}

// round 13
// speedup vs baseline: 1.0239x; 1.0031x over previous
#include <cuda_runtime.h>
#include <cuda_bf16.h>
#include <cstdint>

// ---------------------------------------------------------------------------
// total = -(1/L) * sum_i dot(q_hat_i, q_real_i)
//       + sum_{i,j} max(0, <pred_i, gt_j> - <pred_i, gt_i> + 1)
// L=8192, B=4096, D=1024.
// R13: GEMM byte-identical to R10 (best: 1024 CTAs, fp8 e4m3, warp tile
// 64x32, 3-stage, 2 CTA/SM; R12's reorder+unroll regressed and is reverted).
// Scheduling change: local_kernel now waits for prep (event) and runs with
// only 152 CTAs, co-resident UNDER the GEMM (which leaves ~8K regs + 1536
// thread slots per SM free and 99% of DRAM idle).
// ---------------------------------------------------------------------------

#define L_DIM 8192
#define B_DIM 4096
#define D_DIM 1024

struct Accum {
    double glob;
    double local;
    unsigned int gticket;
    unsigned int lticket;
    unsigned int local_done;
};
__device__ Accum g_acc;
__device__ float g_pos[B_DIM];
// FP8 operand buffers (4 MB each), stored as uint32 (4 e4m3 per word)
__device__ uint32_t g_predq[(size_t)B_DIM * D_DIM / 4];
__device__ uint32_t g_gtq[(size_t)B_DIM * D_DIM / 4];

#define NUM_GEMM_CTAS (32 * 32)
#define NUM_LOCAL_CTAS 152
#define PREP_ROWS 4

// ---------------------------------------------------------------------------
__device__ __forceinline__ uint32_t smem_u32(const void* p) {
    uint32_t a;
    asm("{ .reg .u64 t; cvta.to.shared.u64 t, %1; cvt.u32.u64 %0, t; }"
        : "=r"(a) : "l"(p));
    return a;
}

__device__ __forceinline__ void cp_async16(uint32_t smem, const void* gmem) {
    asm volatile("cp.async.cg.shared.global [%0], [%1], 16;"
                 :: "r"(smem), "l"(gmem) : "memory");
}
#define CP_COMMIT() asm volatile("cp.async.commit_group;" ::: "memory")
#define CP_WAIT1()  asm volatile("cp.async.wait_group 1;" ::: "memory")

#define LDSM_X4(r0, r1, r2, r3, addr) \
    asm volatile("ldmatrix.sync.aligned.m8n8.x4.shared.b16 {%0,%1,%2,%3}, [%4];" \
                 : "=r"(r0), "=r"(r1), "=r"(r2), "=r"(r3) : "r"(addr))

// FP8 e4m3 MMA, k32, fp32 accumulation.
__device__ __forceinline__ void mma16832(float* c, const uint32_t* a,
                                         uint32_t b0, uint32_t b1) {
    asm volatile(
        "mma.sync.aligned.m16n8k32.row.col.f32.e4m3.e4m3.f32 "
        "{%0,%1,%2,%3}, {%4,%5,%6,%7}, {%8,%9}, {%0,%1,%2,%3};"
        : "+f"(c[0]), "+f"(c[1]), "+f"(c[2]), "+f"(c[3])
        : "r"(a[0]), "r"(a[1]), "r"(a[2]), "r"(a[3]), "r"(b0), "r"(b1));
}

__device__ __forceinline__ uint32_t pack_e4m3x4(float4 v) {
    uint16_t lo, hi;
    asm("cvt.rn.satfinite.e4m3x2.f32 %0, %1, %2;" : "=h"(lo) : "f"(v.y), "f"(v.x));
    asm("cvt.rn.satfinite.e4m3x2.f32 %0, %1, %2;" : "=h"(hi) : "f"(v.w), "f"(v.z));
    return (uint32_t)lo | ((uint32_t)hi << 16);
}

// ---------------------------------------------------------------------------
// Kernel 1: fp32 -> e4m3 for pred/gt + pos[i] = dot(pred_i, gt_i) (exact fp32)
// 4 rows per block (8 independent 16B loads in flight per thread).
// ---------------------------------------------------------------------------
__global__ void prep_kernel(const float* __restrict__ pred,
                            const float* __restrict__ gt) {
    const int r0 = blockIdx.x * PREP_ROWS;
    const int t = threadIdx.x;

    float4 pv[PREP_ROWS], gv[PREP_ROWS];
    #pragma unroll
    for (int rr = 0; rr < PREP_ROWS; rr++) {
        pv[rr] = ((const float4*)(pred + (size_t)(r0 + rr) * D_DIM))[t];
        gv[rr] = ((const float4*)(gt + (size_t)(r0 + rr) * D_DIM))[t];
    }

    __shared__ float ws[PREP_ROWS][8];
    #pragma unroll
    for (int rr = 0; rr < PREP_ROWS; rr++) {
        g_predq[(size_t)(r0 + rr) * (D_DIM / 4) + t] = pack_e4m3x4(pv[rr]);
        g_gtq[(size_t)(r0 + rr) * (D_DIM / 4) + t] = pack_e4m3x4(gv[rr]);

        float acc = pv[rr].x * gv[rr].x + pv[rr].y * gv[rr].y +
                    pv[rr].z * gv[rr].z + pv[rr].w * gv[rr].w;
        #pragma unroll
        for (int o = 16; o > 0; o >>= 1)
            acc += __shfl_xor_sync(0xFFFFFFFFu, acc, o);
        if ((t & 31) == 0) ws[rr][t >> 5] = acc;
    }
    __syncthreads();
    if (t < PREP_ROWS) {
        float s = 0.f;
        #pragma unroll
        for (int w = 0; w < 8; w++) s += ws[t][w];
        g_pos[r0 + t] = s;
    }
}

// ---------------------------------------------------------------------------
// Kernel 2: local loss partial. 152 CTAs — sized to co-reside under the GEMM
// (GEMM leaves ~8K regs and 1536 thread slots per SM; its DRAM is ~1% busy).
// Last block sets local_done for the GEMM's fused finalize.
// ---------------------------------------------------------------------------
__global__ void local_kernel(const float* __restrict__ a,
                             const float* __restrict__ b) {
    const size_t n4 = (size_t)L_DIM * D_DIM / 4;
    float acc = 0.f;
    for (size_t i = (size_t)blockIdx.x * blockDim.x + threadIdx.x; i < n4;
         i += (size_t)gridDim.x * blockDim.x) {
        float4 av = ((const float4*)a)[i];
        float4 bv = ((const float4*)b)[i];
        acc += av.x * bv.x + av.y * bv.y + av.z * bv.z + av.w * bv.w;
    }
    #pragma unroll
    for (int o = 16; o > 0; o >>= 1)
        acc += __shfl_xor_sync(0xFFFFFFFFu, acc, o);
    __shared__ float ws[8];
    const int t = threadIdx.x;
    if ((t & 31) == 0) ws[t >> 5] = acc;
    __syncthreads();
    if (t == 0) {
        float s = 0.f;
        #pragma unroll
        for (int w = 0; w < 8; w++) s += ws[w];
        atomicAdd(&g_acc.local, (double)s);
        __threadfence();
        unsigned int tk = atomicAdd(&g_acc.lticket, 1u);
        if (tk == NUM_LOCAL_CTAS - 1) {
            __threadfence();
            atomicExch(&g_acc.local_done, 1u);
        }
    }
}

// ---------------------------------------------------------------------------
// Kernel 3: FP8 GEMM 128x128 tile + fused hinge + fused finalize.
// Byte-identical mainloop to R10: grid (32,32), 256 thr, 8 warps 2x4,
// warp tile 64x32, 3-stage cp.async (wait1 -> sync -> load -> commit),
// 2 CTAs/SM, rolled kc loop.
// ---------------------------------------------------------------------------
static constexpr int GEMM_SMEM_DYN = 3 * 32768;  // 96 KB

__global__ void __launch_bounds__(256, 2) gemm_hinge_kernel(float* out) {
    extern __shared__ char smem_raw[];
    const uint32_t sb = smem_u32(smem_raw);
    const int tid = threadIdx.x;
    const int wid = tid >> 5;
    const int lane = tid & 31;
    const int warp_m = wid >> 2;   // 0..1
    const int warp_n = wid & 3;    // 0..3

    const uint8_t* __restrict__ Ab =
        (const uint8_t*)g_predq + (size_t)blockIdx.y * 128 * D_DIM;
    const uint8_t* __restrict__ Bb =
        (const uint8_t*)g_gtq + (size_t)blockIdx.x * 128 * D_DIM;

    // Precomputed LDSM base offsets: addr = stage_base + (base ^ (chunk<<4))
    uint32_t a_base[4], b_base[2];
    #pragma unroll
    for (int mt = 0; mt < 4; mt++) {
        const int row = warp_m * 64 + mt * 16 + (lane & 15);
        a_base[mt] = row * 128 + (((lane >> 4) ^ (row & 7)) << 4);
    }
    #pragma unroll
    for (int nt = 0; nt < 2; nt++) {
        const int row = warp_n * 32 + nt * 16 + (lane & 15);
        b_base[nt] = row * 128 + (((lane >> 4) ^ (row & 7)) << 4);
    }

    float acc[4][4][4];
    #pragma unroll
    for (int i = 0; i < 4; i++)
        #pragma unroll
        for (int j = 0; j < 4; j++)
            #pragma unroll
            for (int e = 0; e < 4; e++) acc[i][j][e] = 0.f;

    // Load one K-chunk (128 B per row) of A and B into stage st.
    auto load_stage = [&](int kc, int st) {
        const uint32_t baseA = sb + st * 32768;
        const uint32_t baseB = baseA + 16384;
        #pragma unroll
        for (int i = 0; i < 4; i++) {
            const int idx = tid + i * 256;      // 0..1023
            const int row = idx >> 3;           // 0..127
            const int c = idx & 7;              // 16B chunk within 128B row
            const uint32_t soff = row * 128 + ((c ^ (row & 7)) << 4);
            cp_async16(baseA + soff, Ab + (size_t)row * D_DIM + kc * 128 + c * 16);
            cp_async16(baseB + soff, Bb + (size_t)row * D_DIM + kc * 128 + c * 16);
        }
    };

    load_stage(0, 0); CP_COMMIT();
    load_stage(1, 1); CP_COMMIT();

    #pragma unroll 1
    for (int kc = 0; kc < 8; ++kc) {
        CP_WAIT1();          // stage kc resident
        __syncthreads();     // all warps done with the stage we refill
        if (kc + 2 < 8) load_stage(kc + 2, (kc + 2) % 3);
        CP_COMMIT();         // uniform group count even when empty

        const uint32_t baseA = sb + (kc % 3) * 32768;
        const uint32_t baseB = baseA + 16384;

        #pragma unroll
        for (int ks = 0; ks < 4; ks++) {   // four k32 steps per 128-B chunk
            const uint32_t cx = (uint32_t)(ks * 2) << 4;  // chunk XOR offset
            uint32_t a[4][4], b[2][4];
            #pragma unroll
            for (int mt = 0; mt < 4; mt++)
                LDSM_X4(a[mt][0], a[mt][1], a[mt][2], a[mt][3],
                        baseA + (a_base[mt] ^ cx));
            #pragma unroll
            for (int nt = 0; nt < 2; nt++)
                LDSM_X4(b[nt][0], b[nt][1], b[nt][2], b[nt][3],
                        baseB + (b_base[nt] ^ cx));
            #pragma unroll
            for (int mt = 0; mt < 4; mt++)
                #pragma unroll
                for (int nt = 0; nt < 4; nt++)
                    mma16832(acc[mt][nt], a[mt],
                             b[nt >> 1][nt & 1], b[nt >> 1][(nt & 1) + 2]);
        }
    }

    // ---- fused hinge epilogue ----
    float partial = 0.f;
    #pragma unroll
    for (int mt = 0; mt < 4; mt++) {
        const int r0 = blockIdx.y * 128 + warp_m * 64 + mt * 16 + (lane >> 2);
        const float p0 = __ldg(&g_pos[r0]) - 1.0f;   // v - pos + 1 = v - (pos-1)
        const float p1 = __ldg(&g_pos[r0 + 8]) - 1.0f;
        #pragma unroll
        for (int nt = 0; nt < 4; nt++) {
            partial += fmaxf(acc[mt][nt][0] - p0, 0.f);
            partial += fmaxf(acc[mt][nt][1] - p0, 0.f);
            partial += fmaxf(acc[mt][nt][2] - p1, 0.f);
            partial += fmaxf(acc[mt][nt][3] - p1, 0.f);
        }
    }

    #pragma unroll
    for (int o = 16; o > 0; o >>= 1)
        partial += __shfl_xor_sync(0xFFFFFFFFu, partial, o);
    __shared__ float warpsum[8];
    if (lane == 0) warpsum[wid] = partial;
    __syncthreads();
    if (tid == 0) {
        float s = 0.f;
        #pragma unroll
        for (int w = 0; w < 8; w++) s += warpsum[w];
        atomicAdd(&g_acc.glob, (double)s);
        __threadfence();
        unsigned int tk = atomicAdd(&g_acc.gticket, 1u);
        if (tk == NUM_GEMM_CTAS - 1) {
            // Fused finalize: wait for local completion. Deadlock-free: as
            // GEMM CTAs retire, freed slots schedule local's 152 CTAs.
            while (atomicAdd(&g_acc.local_done, 0u) == 0u) {}
            __threadfence();
            const double gv = *((volatile double*)&g_acc.glob);
            const double lv = *((volatile double*)&g_acc.local);
            out[0] = (float)(gv - lv / (double)L_DIM);
        }
    }
}

// ---------------------------------------------------------------------------
extern "C" void kernel_launch(void* const* d_in, const int* in_sizes, int n_in,
                              void* d_out, int out_size) {
    const float* q_hat  = (const float*)d_in[0];
    const float* q_real = (const float*)d_in[1];
    const float* gt     = (const float*)d_in[2];
    const float* pred   = (const float*)d_in[3];

    (void)in_sizes; (void)n_in; (void)out_size;

    // One-time setup on the first (non-captured) correctness call.
    static cudaStream_t s_side = nullptr;
    static cudaEvent_t ev_prep = nullptr, ev_join = nullptr;
    static void* accum_ptr = nullptr;
    if (!accum_ptr) {
        cudaFuncSetAttribute(gemm_hinge_kernel,
                             cudaFuncAttributeMaxDynamicSharedMemorySize,
                             GEMM_SMEM_DYN);
        cudaStreamCreateWithFlags(&s_side, cudaStreamNonBlocking);
        cudaEventCreateWithFlags(&ev_prep, cudaEventDisableTiming);
        cudaEventCreateWithFlags(&ev_join, cudaEventDisableTiming);
        cudaGetSymbolAddress(&accum_ptr, g_acc);
    }

    // Main stream: memset -> prep -> gemm(+finalize)
    // Side stream: local_kernel, gated on prep completion so it runs UNDER
    // the GEMM instead of contending with prep.
    cudaMemsetAsync(accum_ptr, 0, sizeof(Accum), 0);

    prep_kernel<<<B_DIM / PREP_ROWS, 256>>>(pred, gt);
    cudaEventRecord(ev_prep, 0);
    cudaStreamWaitEvent(s_side, ev_prep, 0);

    local_kernel<<<NUM_LOCAL_CTAS, 256, 0, s_side>>>(q_hat, q_real);
    gemm_hinge_kernel<<<dim3(32, 32), 256, GEMM_SMEM_DYN>>>((float*)d_out);

    // Graph must join the side stream before capture ends.
    cudaEventRecord(ev_join, s_side);
    cudaStreamWaitEvent(0, ev_join, 0);
}

// round 14
// speedup vs baseline: 1.1296x; 1.1032x over previous
#include <cuda_runtime.h>
#include <cuda_bf16.h>
#include <cstdint>

// ---------------------------------------------------------------------------
// total = -(1/L) * sum_i dot(q_hat_i, q_real_i)
//       + sum_{i,j} max(0, <pred_i, gt_j> - <pred_i, gt_i> + 1)
// L=8192, B=4096, D=1024.
// R14: local_kernel folded into the GEMM prologue (each CTA does a 1/1024
// slice of the local sum before its tile), and the GEMM launches CONCURRENT
// with prep: per-128-row-block readiness counters (bumped by prep, spun on
// by GEMM CTAs) replace the stream dependency. GEMM mainloop = R10 bytes
// (best measured). No separate local kernel, no local_done spin.
// ---------------------------------------------------------------------------

#define L_DIM 8192
#define B_DIM 4096
#define D_DIM 1024

struct Accum {
    double glob;
    double local;
    unsigned int gticket;
    unsigned int rb_cnt[32];   // per-128-row-block prep completion counters
};
__device__ Accum g_acc;
__device__ float g_pos[B_DIM];
// FP8 operand buffers (4 MB each), stored as uint32 (4 e4m3 per word)
__device__ uint32_t g_predq[(size_t)B_DIM * D_DIM / 4];
__device__ uint32_t g_gtq[(size_t)B_DIM * D_DIM / 4];

#define NUM_GEMM_CTAS (32 * 32)
#define PREP_ROWS 4
#define PREP_BLOCKS_PER_RB 32   // 32 blocks x 4 rows = 128-row block

// ---------------------------------------------------------------------------
__device__ __forceinline__ uint32_t smem_u32(const void* p) {
    uint32_t a;
    asm("{ .reg .u64 t; cvta.to.shared.u64 t, %1; cvt.u32.u64 %0, t; }"
        : "=r"(a) : "l"(p));
    return a;
}

__device__ __forceinline__ void cp_async16(uint32_t smem, const void* gmem) {
    asm volatile("cp.async.cg.shared.global [%0], [%1], 16;"
                 :: "r"(smem), "l"(gmem) : "memory");
}
#define CP_COMMIT() asm volatile("cp.async.commit_group;" ::: "memory")
#define CP_WAIT1()  asm volatile("cp.async.wait_group 1;" ::: "memory")

#define LDSM_X4(r0, r1, r2, r3, addr) \
    asm volatile("ldmatrix.sync.aligned.m8n8.x4.shared.b16 {%0,%1,%2,%3}, [%4];" \
                 : "=r"(r0), "=r"(r1), "=r"(r2), "=r"(r3) : "r"(addr))

// FP8 e4m3 MMA, k32, fp32 accumulation.
__device__ __forceinline__ void mma16832(float* c, const uint32_t* a,
                                         uint32_t b0, uint32_t b1) {
    asm volatile(
        "mma.sync.aligned.m16n8k32.row.col.f32.e4m3.e4m3.f32 "
        "{%0,%1,%2,%3}, {%4,%5,%6,%7}, {%8,%9}, {%0,%1,%2,%3};"
        : "+f"(c[0]), "+f"(c[1]), "+f"(c[2]), "+f"(c[3])
        : "r"(a[0]), "r"(a[1]), "r"(a[2]), "r"(a[3]), "r"(b0), "r"(b1));
}

__device__ __forceinline__ uint32_t pack_e4m3x4(float4 v) {
    uint16_t lo, hi;
    asm("cvt.rn.satfinite.e4m3x2.f32 %0, %1, %2;" : "=h"(lo) : "f"(v.y), "f"(v.x));
    asm("cvt.rn.satfinite.e4m3x2.f32 %0, %1, %2;" : "=h"(hi) : "f"(v.w), "f"(v.z));
    return (uint32_t)lo | ((uint32_t)hi << 16);
}

// ---------------------------------------------------------------------------
// Kernel 1: fp32 -> e4m3 for pred/gt + pos[i] = dot(pred_i, gt_i) (exact fp32)
// 4 rows per block; on completion bumps its 128-row block's readiness counter
// (release: threadfence before the atomic).
// ---------------------------------------------------------------------------
__global__ void prep_kernel(const float* __restrict__ pred,
                            const float* __restrict__ gt) {
    const int r0 = blockIdx.x * PREP_ROWS;
    const int t = threadIdx.x;

    float4 pv[PREP_ROWS], gv[PREP_ROWS];
    #pragma unroll
    for (int rr = 0; rr < PREP_ROWS; rr++) {
        pv[rr] = ((const float4*)(pred + (size_t)(r0 + rr) * D_DIM))[t];
        gv[rr] = ((const float4*)(gt + (size_t)(r0 + rr) * D_DIM))[t];
    }

    __shared__ float ws[PREP_ROWS][8];
    #pragma unroll
    for (int rr = 0; rr < PREP_ROWS; rr++) {
        g_predq[(size_t)(r0 + rr) * (D_DIM / 4) + t] = pack_e4m3x4(pv[rr]);
        g_gtq[(size_t)(r0 + rr) * (D_DIM / 4) + t] = pack_e4m3x4(gv[rr]);

        float acc = pv[rr].x * gv[rr].x + pv[rr].y * gv[rr].y +
                    pv[rr].z * gv[rr].z + pv[rr].w * gv[rr].w;
        #pragma unroll
        for (int o = 16; o > 0; o >>= 1)
            acc += __shfl_xor_sync(0xFFFFFFFFu, acc, o);
        if ((t & 31) == 0) ws[rr][t >> 5] = acc;
    }
    __syncthreads();
    if (t < PREP_ROWS) {
        float s = 0.f;
        #pragma unroll
        for (int w = 0; w < 8; w++) s += ws[t][w];
        g_pos[r0 + t] = s;
    }
    __syncthreads();            // all quant stores + pos stores done
    if (t == 0) {
        __threadfence();        // release
        atomicAdd(&g_acc.rb_cnt[blockIdx.x >> 5], 1u);
    }
}

// ---------------------------------------------------------------------------
// Kernel 2: FP8 GEMM 128x128 tile + fused local-slice + hinge + finalize.
// grid (32,32), 256 thr, 8 warps 2x4, warp tile 64x32, 3-stage cp.async,
// 2 CTAs/SM. Prologue: 1/1024 slice of the local dot-sum (useful work while
// prep finishes), then spin on the two rowblock counters. Mainloop = R10.
// ---------------------------------------------------------------------------
static constexpr int GEMM_SMEM_DYN = 3 * 32768;  // 96 KB

__global__ void __launch_bounds__(256, 2) gemm_hinge_kernel(
        float* out, const float* __restrict__ q_hat,
        const float* __restrict__ q_real) {
    extern __shared__ char smem_raw[];
    const uint32_t sb = smem_u32(smem_raw);
    const int tid = threadIdx.x;
    const int wid = tid >> 5;
    const int lane = tid & 31;
    const int warp_m = wid >> 2;   // 0..1
    const int warp_n = wid & 3;    // 0..3

    // ---- local-loss slice: this CTA covers 8192 floats of the L*D sweep ----
    {
        const size_t cta_id = (size_t)blockIdx.y * 32 + blockIdx.x;
        const size_t base4 = cta_id * 2048;       // float4 index; 1024*2048 = L*D/4
        float acc = 0.f;
        #pragma unroll
        for (int i = 0; i < 8; i++) {
            const float4 av = ((const float4*)q_hat)[base4 + tid + i * 256];
            const float4 bv = ((const float4*)q_real)[base4 + tid + i * 256];
            acc += av.x * bv.x + av.y * bv.y + av.z * bv.z + av.w * bv.w;
        }
        #pragma unroll
        for (int o = 16; o > 0; o >>= 1)
            acc += __shfl_xor_sync(0xFFFFFFFFu, acc, o);
        float* lsum = (float*)smem_raw;           // smem not yet used by pipeline
        if (lane == 0) lsum[wid] = acc;
        __syncthreads();
        if (tid == 0) {
            float s = 0.f;
            #pragma unroll
            for (int w = 0; w < 8; w++) s += lsum[w];
            atomicAdd(&g_acc.local, (double)s);
        }
    }

    // ---- wait until prep finished our A (by) and B (bx) rowblocks ----
    if (tid == 0) {
        while (atomicAdd(&g_acc.rb_cnt[blockIdx.y], 0u) < PREP_BLOCKS_PER_RB ||
               atomicAdd(&g_acc.rb_cnt[blockIdx.x], 0u) < PREP_BLOCKS_PER_RB)
            __nanosleep(200);
        __threadfence();        // acquire
    }
    __syncthreads();            // also retires the lsum smem usage

    const uint8_t* __restrict__ Ab =
        (const uint8_t*)g_predq + (size_t)blockIdx.y * 128 * D_DIM;
    const uint8_t* __restrict__ Bb =
        (const uint8_t*)g_gtq + (size_t)blockIdx.x * 128 * D_DIM;

    // Precomputed LDSM base offsets: addr = stage_base + (base ^ (chunk<<4))
    uint32_t a_base[4], b_base[2];
    #pragma unroll
    for (int mt = 0; mt < 4; mt++) {
        const int row = warp_m * 64 + mt * 16 + (lane & 15);
        a_base[mt] = row * 128 + (((lane >> 4) ^ (row & 7)) << 4);
    }
    #pragma unroll
    for (int nt = 0; nt < 2; nt++) {
        const int row = warp_n * 32 + nt * 16 + (lane & 15);
        b_base[nt] = row * 128 + (((lane >> 4) ^ (row & 7)) << 4);
    }

    float acc[4][4][4];
    #pragma unroll
    for (int i = 0; i < 4; i++)
        #pragma unroll
        for (int j = 0; j < 4; j++)
            #pragma unroll
            for (int e = 0; e < 4; e++) acc[i][j][e] = 0.f;

    // Load one K-chunk (128 B per row) of A and B into stage st.
    auto load_stage = [&](int kc, int st) {
        const uint32_t baseA = sb + st * 32768;
        const uint32_t baseB = baseA + 16384;
        #pragma unroll
        for (int i = 0; i < 4; i++) {
            const int idx = tid + i * 256;      // 0..1023
            const int row = idx >> 3;           // 0..127
            const int c = idx & 7;              // 16B chunk within 128B row
            const uint32_t soff = row * 128 + ((c ^ (row & 7)) << 4);
            cp_async16(baseA + soff, Ab + (size_t)row * D_DIM + kc * 128 + c * 16);
            cp_async16(baseB + soff, Bb + (size_t)row * D_DIM + kc * 128 + c * 16);
        }
    };

    load_stage(0, 0); CP_COMMIT();
    load_stage(1, 1); CP_COMMIT();

    #pragma unroll 1
    for (int kc = 0; kc < 8; ++kc) {
        CP_WAIT1();          // stage kc resident
        __syncthreads();     // all warps done with the stage we refill
        if (kc + 2 < 8) load_stage(kc + 2, (kc + 2) % 3);
        CP_COMMIT();         // uniform group count even when empty

        const uint32_t baseA = sb + (kc % 3) * 32768;
        const uint32_t baseB = baseA + 16384;

        #pragma unroll
        for (int ks = 0; ks < 4; ks++) {   // four k32 steps per 128-B chunk
            const uint32_t cx = (uint32_t)(ks * 2) << 4;  // chunk XOR offset
            uint32_t a[4][4], b[2][4];
            #pragma unroll
            for (int mt = 0; mt < 4; mt++)
                LDSM_X4(a[mt][0], a[mt][1], a[mt][2], a[mt][3],
                        baseA + (a_base[mt] ^ cx));
            #pragma unroll
            for (int nt = 0; nt < 2; nt++)
                LDSM_X4(b[nt][0], b[nt][1], b[nt][2], b[nt][3],
                        baseB + (b_base[nt] ^ cx));
            #pragma unroll
            for (int mt = 0; mt < 4; mt++)
                #pragma unroll
                for (int nt = 0; nt < 4; nt++)
                    mma16832(acc[mt][nt], a[mt],
                             b[nt >> 1][nt & 1], b[nt >> 1][(nt & 1) + 2]);
        }
    }

    // ---- fused hinge epilogue ----
    float partial = 0.f;
    #pragma unroll
    for (int mt = 0; mt < 4; mt++) {
        const int r0 = blockIdx.y * 128 + warp_m * 64 + mt * 16 + (lane >> 2);
        const float p0 = __ldg(&g_pos[r0]) - 1.0f;   // v - pos + 1 = v - (pos-1)
        const float p1 = __ldg(&g_pos[r0 + 8]) - 1.0f;
        #pragma unroll
        for (int nt = 0; nt < 4; nt++) {
            partial += fmaxf(acc[mt][nt][0] - p0, 0.f);
            partial += fmaxf(acc[mt][nt][1] - p0, 0.f);
            partial += fmaxf(acc[mt][nt][2] - p1, 0.f);
            partial += fmaxf(acc[mt][nt][3] - p1, 0.f);
        }
    }

    #pragma unroll
    for (int o = 16; o > 0; o >>= 1)
        partial += __shfl_xor_sync(0xFFFFFFFFu, partial, o);
    __shared__ float warpsum[8];
    if (lane == 0) warpsum[wid] = partial;
    __syncthreads();
    if (tid == 0) {
        float s = 0.f;
        #pragma unroll
        for (int w = 0; w < 8; w++) s += warpsum[w];
        atomicAdd(&g_acc.glob, (double)s);
        __threadfence();
        unsigned int tk = atomicAdd(&g_acc.gticket, 1u);
        if (tk == NUM_GEMM_CTAS - 1) {
            // All CTAs did their local slice before their epilogue, so
            // g_acc.local is complete — no wait needed.
            __threadfence();
            const double gv = *((volatile double*)&g_acc.glob);
            const double lv = *((volatile double*)&g_acc.local);
            out[0] = (float)(gv - lv / (double)L_DIM);
        }
    }
}

// ---------------------------------------------------------------------------
extern "C" void kernel_launch(void* const* d_in, const int* in_sizes, int n_in,
                              void* d_out, int out_size) {
    const float* q_hat  = (const float*)d_in[0];
    const float* q_real = (const float*)d_in[1];
    const float* gt     = (const float*)d_in[2];
    const float* pred   = (const float*)d_in[3];

    (void)in_sizes; (void)n_in; (void)out_size;

    // One-time setup on the first (non-captured) correctness call.
    static cudaStream_t s_side = nullptr;
    static cudaEvent_t ev_fork = nullptr, ev_join = nullptr;
    static void* accum_ptr = nullptr;
    if (!accum_ptr) {
        cudaFuncSetAttribute(gemm_hinge_kernel,
                             cudaFuncAttributeMaxDynamicSharedMemorySize,
                             GEMM_SMEM_DYN);
        cudaStreamCreateWithFlags(&s_side, cudaStreamNonBlocking);
        cudaEventCreateWithFlags(&ev_fork, cudaEventDisableTiming);
        cudaEventCreateWithFlags(&ev_join, cudaEventDisableTiming);
        cudaGetSymbolAddress(&accum_ptr, g_acc);
    }

    // memset -> { prep (side, submitted first), gemm (main) } concurrent.
    // GEMM CTAs self-synchronize on prep via rb_cnt counters; prep can always
    // co-schedule beside resident GEMM CTAs (256 thr / 8K regs / 128 B smem
    // fit in the SM residue next to 2 GEMM CTAs).
    cudaMemsetAsync(accum_ptr, 0, sizeof(Accum), 0);
    cudaEventRecord(ev_fork, 0);
    cudaStreamWaitEvent(s_side, ev_fork, 0);

    prep_kernel<<<B_DIM / PREP_ROWS, 256, 0, s_side>>>(pred, gt);
    gemm_hinge_kernel<<<dim3(32, 32), 256, GEMM_SMEM_DYN>>>(
        (float*)d_out, q_hat, q_real);

    // Graph end must cover prep (side stream).
    cudaEventRecord(ev_join, s_side);
    cudaStreamWaitEvent(0, ev_join, 0);
}